// round 3
// baseline (speedup 1.0000x reference)
#include <cuda_runtime.h>
#include <math.h>

#define BB 16
#define NN 64
#define TT 50
#define DD 4
#define NEMB 128
#define EPS 1e-20f

typedef unsigned long long ull;

__device__ __forceinline__ ull pk2(float a, float b) {
    ull r; asm("mov.b64 %0, {%1,%2};" : "=l"(r) : "f"(a), "f"(b)); return r;
}
__device__ __forceinline__ void upk2(ull p, float& a, float& b) {
    asm("mov.b64 {%0,%1}, %2;" : "=f"(a), "=f"(b) : "l"(p));
}
__device__ __forceinline__ ull fma2(ull a, ull b, ull c) {
    ull r; asm("fma.rn.f32x2 %0, %1, %2, %3;" : "=l"(r) : "l"(a), "l"(b), "l"(c));
    return r;
}

__device__ __forceinline__ float selu_f(float v) {
    const float scale  = 1.0507009873554805f;
    const float salpha = 1.7580993408473766f;   // scale * alpha
    float e   = __expf(v);
    float neg = salpha * e - salpha;
    float pos = scale * v;
    return v > 0.f ? pos : neg;
}

__global__ __launch_bounds__(256, 4)
void gcn_fused_kernel(const float* __restrict__ x,
                      const float* __restrict__ Wc,
                      const float* __restrict__ bc,
                      const float* __restrict__ Ws,
                      const float* __restrict__ bs,
                      float* __restrict__ out)
{
    const int bt  = blockIdx.x;
    const int b   = bt / TT;
    const int t   = bt % TT;
    const int tid = threadIdx.x;

    __shared__ float4 sx[NN];     // x[b, :, t, :]
    __shared__ float4 sxd[NN];    // dinv[m] * x[m]
    __shared__ float4 sy[NN];     // normalized conv input

    // ---- load x tile ----
    if (tid < NN) {
        const float4* p = reinterpret_cast<const float4*>(
            x + ((size_t)(b * NN + tid) * TT + t) * DD);
        sx[tid] = *p;
    }
    __syncthreads();

    // ---- phases 1+2: thread (r = tid>>2, q = tid&3) owns m in [16q, 16q+16) ----
    const int r = tid >> 2;
    const int q = tid & 3;

    float wv[16];
    float di;
    {
        const float4 a = sx[r];
        float degp = 0.f;
        #pragma unroll
        for (int k = 0; k < 16; k++) {
            const int m = q * 16 + k;
            const float4 c = sx[m];
            const float d0 = a.x - c.x, d1 = a.y - c.y;
            const float d2 = a.z - c.z, d3 = a.w - c.w;
            const float dd = d0 * d0 + d1 * d1 + d2 * d2 + d3 * d3;
            const float w_ = (m == r) ? 0.f : rsqrtf(dd);  // 1/(||.||+1e-20) ~ rsqrt
            wv[k] = w_;
            degp += w_;
        }
        // reduce degree across the 4 lanes that share node r (adjacent lanes)
        degp += __shfl_xor_sync(0xffffffffu, degp, 1);
        degp += __shfl_xor_sync(0xffffffffu, degp, 2);
        di = rsqrtf(degp + EPS);
        if (q == 0) {
            sxd[r] = make_float4(a.x * di, a.y * di, a.z * di, a.w * di);
        }
    }
    __syncthreads();

    {
        float ax = 0.f, ay = 0.f, az = 0.f, aw = 0.f;
        #pragma unroll
        for (int k = 0; k < 16; k++) {
            const int m = q * 16 + k;
            const float4 v = sxd[m];
            const float w_ = wv[k];
            ax += w_ * v.x; ay += w_ * v.y; az += w_ * v.z; aw += w_ * v.w;
        }
        ax += __shfl_xor_sync(0xffffffffu, ax, 1);
        ay += __shfl_xor_sync(0xffffffffu, ay, 1);
        az += __shfl_xor_sync(0xffffffffu, az, 1);
        aw += __shfl_xor_sync(0xffffffffu, aw, 1);
        ax += __shfl_xor_sync(0xffffffffu, ax, 2);
        ay += __shfl_xor_sync(0xffffffffu, ay, 2);
        az += __shfl_xor_sync(0xffffffffu, az, 2);
        aw += __shfl_xor_sync(0xffffffffu, aw, 2);
        if (q == 0) {
            sy[r] = make_float4(ax * di, ay * di, az * di, aw * di);
        }
    }
    __syncthreads();

    // ---- epilogue: 64 nodes x 256 channels, packed f32x2 dot products ----
    const int rowq = tid >> 6;            // which of 4 node rows per iter
    const int cg   = tid & 63;            // float4 group in the row
    const int cc   = cg * 4;
    const bool is_skip = (cc < NEMB);
    const int ch = is_skip ? cc : (cc - NEMB);
    const float* Wp = is_skip ? Ws : Wc;
    const float* bp = is_skip ? bs : bc;
    const float4* vbase = is_skip ? sx : sy;

    const float4 r0 = *reinterpret_cast<const float4*>(Wp + 0 * NEMB + ch);
    const float4 r1 = *reinterpret_cast<const float4*>(Wp + 1 * NEMB + ch);
    const float4 r2 = *reinterpret_cast<const float4*>(Wp + 2 * NEMB + ch);
    const float4 r3 = *reinterpret_cast<const float4*>(Wp + 3 * NEMB + ch);
    const float4 bb = *reinterpret_cast<const float4*>(bp + ch);

    const ull pa0 = pk2(r0.x, r0.y), pa1 = pk2(r1.x, r1.y);
    const ull pa2 = pk2(r2.x, r2.y), pa3 = pk2(r3.x, r3.y);
    const ull pb0 = pk2(r0.z, r0.w), pb1 = pk2(r1.z, r1.w);
    const ull pb2 = pk2(r2.z, r2.w), pb3 = pk2(r3.z, r3.w);
    const ull bias01 = pk2(bb.x, bb.y);
    const ull bias23 = pk2(bb.z, bb.w);

    float* obase = out + (((size_t)(b * NN) * TT + t) * 2 * NEMB + cc);
    const size_t orow = (size_t)TT * 2 * NEMB;   // stride between node rows

    #pragma unroll
    for (int it = 0; it < 16; it++) {
        const int n = it * 4 + rowq;
        const float4 v = vbase[n];
        const ull vx = pk2(v.x, v.x), vy = pk2(v.y, v.y);
        const ull vz = pk2(v.z, v.z), vw = pk2(v.w, v.w);

        ull a01 = fma2(vx, pa0, bias01);
        a01 = fma2(vy, pa1, a01);
        a01 = fma2(vz, pa2, a01);
        a01 = fma2(vw, pa3, a01);

        ull a23 = fma2(vx, pb0, bias23);
        a23 = fma2(vy, pb1, a23);
        a23 = fma2(vz, pb2, a23);
        a23 = fma2(vw, pb3, a23);

        float o0, o1, o2, o3;
        upk2(a01, o0, o1);
        upk2(a23, o2, o3);
        float4 o = make_float4(selu_f(o0), selu_f(o1), selu_f(o2), selu_f(o3));
        *reinterpret_cast<float4*>(obase + (size_t)n * orow) = o;
    }
}

extern "C" void kernel_launch(void* const* d_in, const int* in_sizes, int n_in,
                              void* d_out, int out_size)
{
    // metadata order: x, rel_rec, rel_send, W_conv, b_conv, W_skip, b_skip
    const float* x  = (const float*)d_in[0];
    const float* Wc = (const float*)d_in[3];
    const float* bc = (const float*)d_in[4];
    const float* Ws = (const float*)d_in[5];
    const float* bs = (const float*)d_in[6];
    float* out = (float*)d_out;

    gcn_fused_kernel<<<BB * TT, 256>>>(x, Wc, bc, Ws, bs, out);
}

// round 4
// speedup vs baseline: 1.1875x; 1.1875x over previous
#include <cuda_runtime.h>
#include <math.h>

#define BB 16
#define NN 64
#define TT 50
#define DD 4
#define NEMB 128
#define EPS 1e-20f

__device__ float4 g_sy[BB * TT * NN];   // normalized conv input per (b,t,n)

__device__ __forceinline__ float selu_f(float v) {
    const float scale  = 1.0507009873554805f;
    const float salpha = 1.7580993408473766f;   // scale * alpha
    float e   = __expf(v);
    float neg = salpha * e - salpha;
    float pos = scale * v;
    return v > 0.f ? pos : neg;
}

// ---------------- Kernel A: adjacency + normalization, sy -> scratch --------
__global__ __launch_bounds__(256)
void gcn_phase_kernel(const float* __restrict__ x)
{
    const int bt  = blockIdx.x;
    const int b   = bt / TT;
    const int t   = bt % TT;
    const int tid = threadIdx.x;

    __shared__ float4 sx[NN];
    __shared__ float4 sxd[NN];
    __shared__ float  w[NN][NN + 1];
    __shared__ float  pdeg[4 * NN];
    __shared__ float4 psum[4 * NN];
    __shared__ float  dinv[NN];

    if (tid < NN) {
        const float4* p = reinterpret_cast<const float4*>(
            x + ((size_t)(b * NN + tid) * TT + t) * DD);
        sx[tid] = *p;
    }
    __syncthreads();

    const int r = tid & 63;
    const int q = tid >> 6;
    {
        const float4 a = sx[r];
        float degp = 0.f;
        #pragma unroll
        for (int k = 0; k < 16; k++) {
            const int m = q * 16 + k;
            const float4 c = sx[m];
            const float d0 = a.x - c.x, d1 = a.y - c.y;
            const float d2 = a.z - c.z, d3 = a.w - c.w;
            const float dd = d0 * d0 + d1 * d1 + d2 * d2 + d3 * d3;
            const float wv = (m == r) ? 0.f : rsqrtf(dd);
            w[r][m] = wv;
            degp += wv;
        }
        pdeg[q * NN + r] = degp;
    }
    __syncthreads();

    if (tid < NN) {
        const float deg = pdeg[tid] + pdeg[NN + tid] + pdeg[2 * NN + tid] + pdeg[3 * NN + tid];
        const float di  = rsqrtf(deg + EPS);
        dinv[tid] = di;
        const float4 v = sx[tid];
        sxd[tid] = make_float4(v.x * di, v.y * di, v.z * di, v.w * di);
    }
    __syncthreads();

    {
        float4 acc = make_float4(0.f, 0.f, 0.f, 0.f);
        #pragma unroll
        for (int k = 0; k < 16; k++) {
            const int m = q * 16 + k;
            const float wv = w[r][m];
            const float4 v = sxd[m];
            acc.x += wv * v.x; acc.y += wv * v.y;
            acc.z += wv * v.z; acc.w += wv * v.w;
        }
        psum[q * NN + r] = acc;
    }
    __syncthreads();

    if (tid < NN) {
        const float4 a0 = psum[tid];
        const float4 a1 = psum[NN + tid];
        const float4 a2 = psum[2 * NN + tid];
        const float4 a3 = psum[3 * NN + tid];
        const float di = dinv[tid];
        g_sy[bt * NN + tid] = make_float4((a0.x + a1.x + a2.x + a3.x) * di,
                                          (a0.y + a1.y + a2.y + a3.y) * di,
                                          (a0.z + a1.z + a2.z + a3.z) * di,
                                          (a0.w + a1.w + a2.w + a3.w) * di);
    }
}

// ---------------- Kernel B: streaming epilogue (4 blocks per (b,t)) ---------
#define NODES_PER_BLK 16

__global__ __launch_bounds__(256)
void gcn_epilogue_kernel(const float* __restrict__ x,
                         const float* __restrict__ Wc,
                         const float* __restrict__ bc,
                         const float* __restrict__ Ws,
                         const float* __restrict__ bs,
                         float* __restrict__ out)
{
    const int bid = blockIdx.x;
    const int bt  = bid >> 2;
    const int ng  = bid & 3;
    const int b   = bt / TT;
    const int t   = bt % TT;
    const int n0  = ng * NODES_PER_BLK;
    const int tid = threadIdx.x;

    __shared__ float4 vsk[NODES_PER_BLK];   // x[b, n0+i, t, :]
    __shared__ float4 vcv[NODES_PER_BLK];   // sy[bt, n0+i, :]

    if (tid < NODES_PER_BLK) {
        vsk[tid] = *reinterpret_cast<const float4*>(
            x + ((size_t)(b * NN + n0 + tid) * TT + t) * DD);
    } else if (tid < 2 * NODES_PER_BLK) {
        vcv[tid - NODES_PER_BLK] = g_sy[bt * NN + n0 + (tid - NODES_PER_BLK)];
    }

    const int rowq = tid >> 6;           // 0..3
    const int cg   = tid & 63;           // float4 channel group
    const int cc   = cg * 4;
    const bool is_skip = (cc < NEMB);
    const int  ch      = is_skip ? cc : (cc - NEMB);
    const float* Wp = is_skip ? Ws : Wc;
    const float* bp = is_skip ? bs : bc;

    const float4 r0 = *reinterpret_cast<const float4*>(Wp + 0 * NEMB + ch);
    const float4 r1 = *reinterpret_cast<const float4*>(Wp + 1 * NEMB + ch);
    const float4 r2 = *reinterpret_cast<const float4*>(Wp + 2 * NEMB + ch);
    const float4 r3 = *reinterpret_cast<const float4*>(Wp + 3 * NEMB + ch);
    const float4 bb = *reinterpret_cast<const float4*>(bp + ch);
    __syncthreads();

    const float4* vbase = is_skip ? vsk : vcv;
    float* obase = out + (((size_t)(b * NN + n0) * TT + t) * 2 * NEMB + cc);
    const size_t orow = (size_t)TT * 2 * NEMB;

    #pragma unroll
    for (int it = 0; it < 4; it++) {
        const int nl = it * 4 + rowq;    // 0..15
        const float4 v = vbase[nl];
        float4 o;
        o.x = selu_f(v.x * r0.x + v.y * r1.x + v.z * r2.x + v.w * r3.x + bb.x);
        o.y = selu_f(v.x * r0.y + v.y * r1.y + v.z * r2.y + v.w * r3.y + bb.y);
        o.z = selu_f(v.x * r0.z + v.y * r1.z + v.z * r2.z + v.w * r3.z + bb.z);
        o.w = selu_f(v.x * r0.w + v.y * r1.w + v.z * r2.w + v.w * r3.w + bb.w);
        *reinterpret_cast<float4*>(obase + (size_t)nl * orow) = o;
    }
}

extern "C" void kernel_launch(void* const* d_in, const int* in_sizes, int n_in,
                              void* d_out, int out_size)
{
    // metadata order: x, rel_rec, rel_send, W_conv, b_conv, W_skip, b_skip
    const float* x  = (const float*)d_in[0];
    const float* Wc = (const float*)d_in[3];
    const float* bc = (const float*)d_in[4];
    const float* Ws = (const float*)d_in[5];
    const float* bs = (const float*)d_in[6];
    float* out = (float*)d_out;

    gcn_phase_kernel<<<BB * TT, 256>>>(x);
    gcn_epilogue_kernel<<<BB * TT * 4, 256>>>(x, Wc, bc, Ws, bs, out);
}

// round 5
// speedup vs baseline: 1.3294x; 1.1195x over previous
#include <cuda_runtime.h>
#include <math.h>

#define BB 16
#define NN 64
#define TT 50
#define DD 4
#define NEMB 128
#define EPS 1e-20f

// scratch: normalized conv input, transposed to [B][N][T] for coalesced reads
__device__ float4 g_sy[BB * NN * TT];

__device__ __forceinline__ float selu_f(float v) {
    const float scale  = 1.0507009873554805f;
    const float salpha = 1.7580993408473766f;   // scale * alpha
    float e   = __expf(v);
    float neg = salpha * e - salpha;
    float pos = scale * v;
    return v > 0.f ? pos : neg;
}

// ---------------- Kernel A: adjacency + normalization, sy -> scratch --------
__global__ __launch_bounds__(256)
void gcn_phase_kernel(const float* __restrict__ x)
{
    const int bt  = blockIdx.x;
    const int b   = bt / TT;
    const int t   = bt % TT;
    const int tid = threadIdx.x;

    __shared__ float4 sx[NN];
    __shared__ float4 sxd[NN];
    __shared__ float  w[NN][NN + 1];
    __shared__ float  pdeg[4 * NN];
    __shared__ float4 psum[4 * NN];
    __shared__ float  dinv[NN];

    if (tid < NN) {
        const float4* p = reinterpret_cast<const float4*>(
            x + ((size_t)(b * NN + tid) * TT + t) * DD);
        sx[tid] = *p;
    }
    __syncthreads();

    const int r = tid & 63;
    const int q = tid >> 6;
    {
        const float4 a = sx[r];
        float degp = 0.f;
        #pragma unroll
        for (int k = 0; k < 16; k++) {
            const int m = q * 16 + k;
            const float4 c = sx[m];
            const float d0 = a.x - c.x, d1 = a.y - c.y;
            const float d2 = a.z - c.z, d3 = a.w - c.w;
            const float dd = d0 * d0 + d1 * d1 + d2 * d2 + d3 * d3;
            const float wv = (m == r) ? 0.f : rsqrtf(dd);
            w[r][m] = wv;
            degp += wv;
        }
        pdeg[q * NN + r] = degp;
    }
    __syncthreads();

    if (tid < NN) {
        const float deg = pdeg[tid] + pdeg[NN + tid] + pdeg[2 * NN + tid] + pdeg[3 * NN + tid];
        const float di  = rsqrtf(deg + EPS);
        dinv[tid] = di;
        const float4 v = sx[tid];
        sxd[tid] = make_float4(v.x * di, v.y * di, v.z * di, v.w * di);
    }
    __syncthreads();

    {
        float4 acc = make_float4(0.f, 0.f, 0.f, 0.f);
        #pragma unroll
        for (int k = 0; k < 16; k++) {
            const int m = q * 16 + k;
            const float wv = w[r][m];
            const float4 v = sxd[m];
            acc.x += wv * v.x; acc.y += wv * v.y;
            acc.z += wv * v.z; acc.w += wv * v.w;
        }
        psum[q * NN + r] = acc;
    }
    __syncthreads();

    if (tid < NN) {
        const float4 a0 = psum[tid];
        const float4 a1 = psum[NN + tid];
        const float4 a2 = psum[2 * NN + tid];
        const float4 a3 = psum[3 * NN + tid];
        const float di = dinv[tid];
        // transposed scratch layout: [b][n][t]
        g_sy[((size_t)b * NN + tid) * TT + t] =
            make_float4((a0.x + a1.x + a2.x + a3.x) * di,
                        (a0.y + a1.y + a2.y + a3.y) * di,
                        (a0.z + a1.z + a2.z + a3.z) * di,
                        (a0.w + a1.w + a2.w + a3.w) * di);
    }
}

// ---------------- Kernel B: epilogue, one block per (b, n) ------------------
__global__ __launch_bounds__(256)
void gcn_epilogue_kernel(const float* __restrict__ x,
                         const float* __restrict__ Wc,
                         const float* __restrict__ bc,
                         const float* __restrict__ Ws,
                         const float* __restrict__ bs,
                         float* __restrict__ out)
{
    const int bn  = blockIdx.x;          // 0 .. B*N-1
    const int tid = threadIdx.x;

    __shared__ float4 vsk[TT];           // x[b, n, :, :]   (contiguous 800 B)
    __shared__ float4 vcv[TT];           // sy[b, n, :]     (contiguous 800 B)

    if (tid < TT) {
        vsk[tid] = reinterpret_cast<const float4*>(x)[(size_t)bn * TT + tid];
    } else if (tid >= 64 && tid < 64 + TT) {
        vcv[tid - 64] = g_sy[(size_t)bn * TT + (tid - 64)];
    }

    // thread -> (rowq = t slot 0..3, cg = channel float4 group 0..63)
    const int rowq = tid >> 6;
    const int cg   = tid & 63;
    const int cc   = cg * 4;
    const bool is_skip = (cc < NEMB);
    const int  ch      = is_skip ? cc : (cc - NEMB);
    const float* Wp = is_skip ? Ws : Wc;
    const float* bp = is_skip ? bs : bc;

    const float4 r0 = *reinterpret_cast<const float4*>(Wp + 0 * NEMB + ch);
    const float4 r1 = *reinterpret_cast<const float4*>(Wp + 1 * NEMB + ch);
    const float4 r2 = *reinterpret_cast<const float4*>(Wp + 2 * NEMB + ch);
    const float4 r3 = *reinterpret_cast<const float4*>(Wp + 3 * NEMB + ch);
    const float4 bb = *reinterpret_cast<const float4*>(bp + ch);
    __syncthreads();

    const float4* vbase = is_skip ? vsk : vcv;
    // out[b, n, t, cc]: row stride over t is 2*NEMB floats
    float4* obase = reinterpret_cast<float4*>(
        out + (size_t)bn * TT * 2 * NEMB + cc);
    const int ostride = 2 * NEMB / 4;    // float4 units per t step

    #pragma unroll
    for (int it = 0; it < 13; it++) {
        const int t = it * 4 + rowq;
        if (t < TT) {
            const float4 v = vbase[t];   // broadcast across 64 threads
            float4 o;
            o.x = selu_f(v.x * r0.x + v.y * r1.x + v.z * r2.x + v.w * r3.x + bb.x);
            o.y = selu_f(v.x * r0.y + v.y * r1.y + v.z * r2.y + v.w * r3.y + bb.y);
            o.z = selu_f(v.x * r0.z + v.y * r1.z + v.z * r2.z + v.w * r3.z + bb.z);
            o.w = selu_f(v.x * r0.w + v.y * r1.w + v.z * r2.w + v.w * r3.w + bb.w);
            obase[(size_t)t * ostride] = o;
        }
    }
}

extern "C" void kernel_launch(void* const* d_in, const int* in_sizes, int n_in,
                              void* d_out, int out_size)
{
    // metadata order: x, rel_rec, rel_send, W_conv, b_conv, W_skip, b_skip
    const float* x  = (const float*)d_in[0];
    const float* Wc = (const float*)d_in[3];
    const float* bc = (const float*)d_in[4];
    const float* Ws = (const float*)d_in[5];
    const float* bs = (const float*)d_in[6];
    float* out = (float*)d_out;

    gcn_phase_kernel<<<BB * TT, 256>>>(x);
    gcn_epilogue_kernel<<<BB * NN, 256>>>(x, Wc, bc, Ws, bs, out);
}